// round 10
// baseline (speedup 1.0000x reference)
#include <cuda_runtime.h>

#define Nn 20000
#define Ee 640000

// ---- scratch (device globals; no allocation allowed) ----
__device__ int g_count[Nn];
__device__ int g_offset[Nn];
__device__ int g_cursor[Nn];
__device__ int g_eidx[Ee];
__device__ int g_total;

// ---- Pass 1: histogram of dst ----
__global__ void hist_kernel(const int* __restrict__ dst) {
    int e = blockIdx.x * blockDim.x + threadIdx.x;
    if (e < Ee) atomicAdd(&g_count[dst[e]], 1);
}

// ---- Pass 2: per-block scan + atomic base allocation (order-free CSR) ----
// Segment order across blocks is nondeterministic but segments are disjoint;
// edge order within a segment is already nondeterministic (scatter atomics),
// and validation is tolerance-based, so this is safe and removes the
// single-block 20-round serial scan.
__global__ void __launch_bounds__(1024)
offset_kernel() {
    __shared__ int wsum[32];
    __shared__ int s_base;
    int tid = threadIdx.x;
    int lane = tid & 31;
    int wid = tid >> 5;
    int i = blockIdx.x * 1024 + tid;
    int v = (i < Nn) ? g_count[i] : 0;
    int x = v;
    #pragma unroll
    for (int off = 1; off < 32; off <<= 1) {
        int y = __shfl_up_sync(0xffffffffu, x, off);
        if (lane >= off) x += y;
    }
    if (lane == 31) wsum[wid] = x;
    __syncthreads();
    if (wid == 0) {
        int w = wsum[lane];
        int xs = w;
        #pragma unroll
        for (int off = 1; off < 32; off <<= 1) {
            int y = __shfl_up_sync(0xffffffffu, xs, off);
            if (lane >= off) xs += y;
        }
        wsum[lane] = xs - w;  // exclusive prefix of warp sums
    }
    __syncthreads();
    int incl = x + wsum[wid];
    int excl = incl - v;
    if (tid == 1023) s_base = atomicAdd(&g_total, incl);
    __syncthreads();
    int b = s_base;
    if (i < Nn) { g_offset[i] = b + excl; g_cursor[i] = b + excl; }
}

// ---- Pass 3: scatter edge ids into CSR order ----
__global__ void scatter_kernel(const int* __restrict__ dst) {
    int e = blockIdx.x * blockDim.x + threadIdx.x;
    if (e < Ee) {
        int n = dst[e];
        int pos = atomicAdd(&g_cursor[n], 1);
        g_eidx[pos] = e;
    }
}

// ---- Pass 4: fused logits + softmax + weighted V, one warp per node ----
// Software-pipelined: edge i+1's key/value loads issued before edge i's
// shuffle/exp/accumulate chain, doubling per-warp MLP.
__global__ void __launch_bounds__(128)
attn_main(const float* __restrict__ value,
          const float* __restrict__ key,
          const float* __restrict__ q0,
          const float* __restrict__ q1,
          float* __restrict__ out) {
    int warp_global = (blockIdx.x * blockDim.x + threadIdx.x) >> 5;
    if (warp_global >= Nn) return;
    const int n = warp_global;
    const int lane = threadIdx.x & 31;

    // per-lane query slice (4 feats of one channel c = lane)
    const float q_a = q0[n * 32 + lane];
    const float q_b = q1[n * 96 + 3 * lane + 0];
    const float q_c = q1[n * 96 + 3 * lane + 1];
    const float q_d = q1[n * 96 + 3 * lane + 2];

    const int start = g_offset[n];
    const int cnt   = g_count[n];

    float acc0 = 0.f, acc1x = 0.f, acc1y = 0.f, acc1z = 0.f;
    float s = 0.f;  // valid on all lanes of each 4-lane head group

    const int srclane_lo = (lane >> 3) << 2;        // head l/8
    const int srclane_hi = srclane_lo + 16;          // head 4 + l/8
    const float scale = 0.08838834764831845f;        // 1/sqrt(128)
    float* __restrict__ prel = out + (size_t)Nn * 128;

    if (cnt > 0) {
        const int last = cnt - 1;
        int e = g_eidx[start];
        // preload edge 0
        float4 k4 = __ldcs(reinterpret_cast<const float4*>(key + (size_t)e * 128 + 4 * lane));
        const float* vr = value + (size_t)e * 192;
        float v0 = __ldcs(vr + 3 * lane);
        float w1 = __ldcs(vr + 96 + 3 * lane + 0);
        float w2 = __ldcs(vr + 96 + 3 * lane + 1);
        float w3 = __ldcs(vr + 96 + 3 * lane + 2);

        for (int i = 0; i < cnt; i++) {
            // ---- prefetch edge i+1 (clamped; always in-bounds, branchless) ----
            int ip = (i + 1 < cnt) ? (i + 1) : last;
            int en = g_eidx[start + ip];
            float4 k4n = __ldcs(reinterpret_cast<const float4*>(key + (size_t)en * 128 + 4 * lane));
            const float* vn = value + (size_t)en * 192;
            float v0n = __ldcs(vn + 3 * lane);
            float w1n = __ldcs(vn + 96 + 3 * lane + 0);
            float w2n = __ldcs(vn + 96 + 3 * lane + 1);
            float w3n = __ldcs(vn + 96 + 3 * lane + 2);

            // ---- compute edge i ----
            float p = k4.x * q_a + k4.y * q_b + k4.z * q_c + k4.w * q_d;
            p += __shfl_xor_sync(0xffffffffu, p, 1);
            p += __shfl_xor_sync(0xffffffffu, p, 2);
            p *= scale;
            float ex = __expf(p);
            if ((lane & 3) == 0) {
                prel[(size_t)e * 8 + (lane >> 2)] = p;  // prelogits output
                s += ex;
            }
            float ex_lo = __shfl_sync(0xffffffffu, ex, srclane_lo);
            float ex_hi = __shfl_sync(0xffffffffu, ex, srclane_hi);

            acc0  += ex_lo * v0;
            acc1x += ex_hi * w1;
            acc1y += ex_hi * w2;
            acc1z += ex_hi * w3;

            // rotate pipeline
            e = en; k4 = k4n; v0 = v0n; w1 = w1n; w2 = w2n; w3 = w3n;
        }
    }

    float s_lo = __shfl_sync(0xffffffffu, s, srclane_lo);
    float s_hi = __shfl_sync(0xffffffffu, s, srclane_hi);
    float inv_lo = (s_lo > 0.f) ? 1.0f / s_lo : 0.0f;
    float inv_hi = (s_hi > 0.f) ? 1.0f / s_hi : 0.0f;

    out[n * 32 + lane] = acc0 * inv_lo;                 // out_0: (N,32,1)
    float* __restrict__ o1 = out + (size_t)Nn * 32;     // out_1: (N,32,3)
    o1[n * 96 + 3 * lane + 0] = acc1x * inv_hi;
    o1[n * 96 + 3 * lane + 1] = acc1y * inv_hi;
    o1[n * 96 + 3 * lane + 2] = acc1z * inv_hi;
}

extern "C" void kernel_launch(void* const* d_in, const int* in_sizes, int n_in,
                              void* d_out, int out_size) {
    const float* value = (const float*)d_in[0];   // (E,64,3)
    const float* key   = (const float*)d_in[1];   // (E,128)
    const float* q0    = (const float*)d_in[2];   // (N,32,1)
    const float* q1    = (const float*)d_in[3];   // (N,32,3)
    const int*   dst   = (const int*)d_in[4];     // (E,)
    float* out = (float*)d_out;                   // out_0 | out_1 | prelogits

    void* pcount = nullptr;
    cudaGetSymbolAddress(&pcount, g_count);
    cudaMemsetAsync(pcount, 0, Nn * sizeof(int));
    void* ptotal = nullptr;
    cudaGetSymbolAddress(&ptotal, g_total);
    cudaMemsetAsync(ptotal, 0, sizeof(int));

    hist_kernel<<<(Ee + 255) / 256, 256>>>(dst);
    offset_kernel<<<(Nn + 1023) / 1024, 1024>>>();
    scatter_kernel<<<(Ee + 255) / 256, 256>>>(dst);
    attn_main<<<(Nn * 32 + 127) / 128, 128>>>(value, key, q0, q1, out);
}

// round 11
// speedup vs baseline: 1.0009x; 1.0009x over previous
#include <cuda_runtime.h>

#define Nn 20000
#define Ee 640000

// ---- scratch (device globals; no allocation allowed) ----
__device__ int g_count[Nn];
__device__ int g_offset[Nn];
__device__ int g_cursor[Nn];
__device__ int g_eidx[Ee];
__device__ int g_total;

// ---- Pass 1: histogram of dst ----
__global__ void hist_kernel(const int* __restrict__ dst) {
    int e = blockIdx.x * blockDim.x + threadIdx.x;
    if (e < Ee) atomicAdd(&g_count[dst[e]], 1);
}

// ---- Pass 2: per-block scan + atomic base allocation (order-free CSR) ----
// Segment order across blocks is nondeterministic but segments are disjoint;
// edge order within a segment is already nondeterministic (scatter atomics),
// and validation is tolerance-based, so this is safe and removes the
// single-block 20-round serial scan.
__global__ void __launch_bounds__(1024)
offset_kernel() {
    __shared__ int wsum[32];
    __shared__ int s_base;
    int tid = threadIdx.x;
    int lane = tid & 31;
    int wid = tid >> 5;
    int i = blockIdx.x * 1024 + tid;
    int v = (i < Nn) ? g_count[i] : 0;
    int x = v;
    #pragma unroll
    for (int off = 1; off < 32; off <<= 1) {
        int y = __shfl_up_sync(0xffffffffu, x, off);
        if (lane >= off) x += y;
    }
    if (lane == 31) wsum[wid] = x;
    __syncthreads();
    if (wid == 0) {
        int w = wsum[lane];
        int xs = w;
        #pragma unroll
        for (int off = 1; off < 32; off <<= 1) {
            int y = __shfl_up_sync(0xffffffffu, xs, off);
            if (lane >= off) xs += y;
        }
        wsum[lane] = xs - w;  // exclusive prefix of warp sums
    }
    __syncthreads();
    int incl = x + wsum[wid];
    int excl = incl - v;
    if (tid == 1023) s_base = atomicAdd(&g_total, incl);
    __syncthreads();
    int b = s_base;
    if (i < Nn) { g_offset[i] = b + excl; g_cursor[i] = b + excl; }
}

// ---- Pass 3: scatter edge ids into CSR order ----
__global__ void scatter_kernel(const int* __restrict__ dst) {
    int e = blockIdx.x * blockDim.x + threadIdx.x;
    if (e < Ee) {
        int n = dst[e];
        int pos = atomicAdd(&g_cursor[n], 1);
        g_eidx[pos] = e;
    }
}

// ---- Pass 4: fused logits + softmax + weighted V, one warp per node ----
// Software-pipelined: edge i+1's key/value loads issued before edge i's
// shuffle/exp/accumulate chain, doubling per-warp MLP.
__global__ void __launch_bounds__(128)
attn_main(const float* __restrict__ value,
          const float* __restrict__ key,
          const float* __restrict__ q0,
          const float* __restrict__ q1,
          float* __restrict__ out) {
    int warp_global = (blockIdx.x * blockDim.x + threadIdx.x) >> 5;
    if (warp_global >= Nn) return;
    const int n = warp_global;
    const int lane = threadIdx.x & 31;

    // per-lane query slice (4 feats of one channel c = lane)
    const float q_a = q0[n * 32 + lane];
    const float q_b = q1[n * 96 + 3 * lane + 0];
    const float q_c = q1[n * 96 + 3 * lane + 1];
    const float q_d = q1[n * 96 + 3 * lane + 2];

    const int start = g_offset[n];
    const int cnt   = g_count[n];

    float acc0 = 0.f, acc1x = 0.f, acc1y = 0.f, acc1z = 0.f;
    float s = 0.f;  // valid on all lanes of each 4-lane head group

    const int srclane_lo = (lane >> 3) << 2;        // head l/8
    const int srclane_hi = srclane_lo + 16;          // head 4 + l/8
    const float scale = 0.08838834764831845f;        // 1/sqrt(128)
    float* __restrict__ prel = out + (size_t)Nn * 128;

    if (cnt > 0) {
        const int last = cnt - 1;
        int e = g_eidx[start];
        // preload edge 0
        float4 k4 = __ldcs(reinterpret_cast<const float4*>(key + (size_t)e * 128 + 4 * lane));
        const float* vr = value + (size_t)e * 192;
        float v0 = __ldcs(vr + 3 * lane);
        float w1 = __ldcs(vr + 96 + 3 * lane + 0);
        float w2 = __ldcs(vr + 96 + 3 * lane + 1);
        float w3 = __ldcs(vr + 96 + 3 * lane + 2);

        for (int i = 0; i < cnt; i++) {
            // ---- prefetch edge i+1 (clamped; always in-bounds, branchless) ----
            int ip = (i + 1 < cnt) ? (i + 1) : last;
            int en = g_eidx[start + ip];
            float4 k4n = __ldcs(reinterpret_cast<const float4*>(key + (size_t)en * 128 + 4 * lane));
            const float* vn = value + (size_t)en * 192;
            float v0n = __ldcs(vn + 3 * lane);
            float w1n = __ldcs(vn + 96 + 3 * lane + 0);
            float w2n = __ldcs(vn + 96 + 3 * lane + 1);
            float w3n = __ldcs(vn + 96 + 3 * lane + 2);

            // ---- compute edge i ----
            float p = k4.x * q_a + k4.y * q_b + k4.z * q_c + k4.w * q_d;
            p += __shfl_xor_sync(0xffffffffu, p, 1);
            p += __shfl_xor_sync(0xffffffffu, p, 2);
            p *= scale;
            float ex = __expf(p);
            if ((lane & 3) == 0) {
                prel[(size_t)e * 8 + (lane >> 2)] = p;  // prelogits output
                s += ex;
            }
            float ex_lo = __shfl_sync(0xffffffffu, ex, srclane_lo);
            float ex_hi = __shfl_sync(0xffffffffu, ex, srclane_hi);

            acc0  += ex_lo * v0;
            acc1x += ex_hi * w1;
            acc1y += ex_hi * w2;
            acc1z += ex_hi * w3;

            // rotate pipeline
            e = en; k4 = k4n; v0 = v0n; w1 = w1n; w2 = w2n; w3 = w3n;
        }
    }

    float s_lo = __shfl_sync(0xffffffffu, s, srclane_lo);
    float s_hi = __shfl_sync(0xffffffffu, s, srclane_hi);
    float inv_lo = (s_lo > 0.f) ? 1.0f / s_lo : 0.0f;
    float inv_hi = (s_hi > 0.f) ? 1.0f / s_hi : 0.0f;

    out[n * 32 + lane] = acc0 * inv_lo;                 // out_0: (N,32,1)
    float* __restrict__ o1 = out + (size_t)Nn * 32;     // out_1: (N,32,3)
    o1[n * 96 + 3 * lane + 0] = acc1x * inv_hi;
    o1[n * 96 + 3 * lane + 1] = acc1y * inv_hi;
    o1[n * 96 + 3 * lane + 2] = acc1z * inv_hi;
}

extern "C" void kernel_launch(void* const* d_in, const int* in_sizes, int n_in,
                              void* d_out, int out_size) {
    const float* value = (const float*)d_in[0];   // (E,64,3)
    const float* key   = (const float*)d_in[1];   // (E,128)
    const float* q0    = (const float*)d_in[2];   // (N,32,1)
    const float* q1    = (const float*)d_in[3];   // (N,32,3)
    const int*   dst   = (const int*)d_in[4];     // (E,)
    float* out = (float*)d_out;                   // out_0 | out_1 | prelogits

    void* pcount = nullptr;
    cudaGetSymbolAddress(&pcount, g_count);
    cudaMemsetAsync(pcount, 0, Nn * sizeof(int));
    void* ptotal = nullptr;
    cudaGetSymbolAddress(&ptotal, g_total);
    cudaMemsetAsync(ptotal, 0, sizeof(int));

    hist_kernel<<<(Ee + 255) / 256, 256>>>(dst);
    offset_kernel<<<(Nn + 1023) / 1024, 1024>>>();
    scatter_kernel<<<(Ee + 255) / 256, 256>>>(dst);
    attn_main<<<(Nn * 32 + 127) / 128, 128>>>(value, key, q0, q1, out);
}

// round 12
// speedup vs baseline: 1.0120x; 1.0110x over previous
#include <cuda_runtime.h>

#define Nn 20000
#define Ee 640000

// ---- scratch (device globals; no allocation allowed) ----
__device__ int g_count[Nn];
__device__ int g_offset[Nn];
__device__ int g_cursor[Nn];
__device__ int g_eidx[Ee];
__device__ int g_total;

// ---- Pass 1: histogram of dst ----
__global__ void hist_kernel(const int* __restrict__ dst) {
    int e = blockIdx.x * blockDim.x + threadIdx.x;
    if (e < Ee) atomicAdd(&g_count[dst[e]], 1);
}

// ---- Pass 2: per-block scan + atomic base allocation (order-free CSR) ----
// Segment order across blocks is nondeterministic but segments are disjoint;
// edge order within a segment is already nondeterministic (scatter atomics),
// and validation is tolerance-based, so this is safe and removes the
// single-block 20-round serial scan.
__global__ void __launch_bounds__(1024)
offset_kernel() {
    __shared__ int wsum[32];
    __shared__ int s_base;
    int tid = threadIdx.x;
    int lane = tid & 31;
    int wid = tid >> 5;
    int i = blockIdx.x * 1024 + tid;
    int v = (i < Nn) ? g_count[i] : 0;
    int x = v;
    #pragma unroll
    for (int off = 1; off < 32; off <<= 1) {
        int y = __shfl_up_sync(0xffffffffu, x, off);
        if (lane >= off) x += y;
    }
    if (lane == 31) wsum[wid] = x;
    __syncthreads();
    if (wid == 0) {
        int w = wsum[lane];
        int xs = w;
        #pragma unroll
        for (int off = 1; off < 32; off <<= 1) {
            int y = __shfl_up_sync(0xffffffffu, xs, off);
            if (lane >= off) xs += y;
        }
        wsum[lane] = xs - w;  // exclusive prefix of warp sums
    }
    __syncthreads();
    int incl = x + wsum[wid];
    int excl = incl - v;
    if (tid == 1023) s_base = atomicAdd(&g_total, incl);
    __syncthreads();
    int b = s_base;
    if (i < Nn) { g_offset[i] = b + excl; g_cursor[i] = b + excl; }
}

// ---- Pass 3: scatter edge ids into CSR order ----
__global__ void scatter_kernel(const int* __restrict__ dst) {
    int e = blockIdx.x * blockDim.x + threadIdx.x;
    if (e < Ee) {
        int n = dst[e];
        int pos = atomicAdd(&g_cursor[n], 1);
        g_eidx[pos] = e;
    }
}

// ---- Pass 4: fused logits + softmax + weighted V, one warp per node ----
// Software-pipelined: edge i+1's key/value loads issued before edge i's
// shuffle/exp/accumulate chain, doubling per-warp MLP.
__global__ void __launch_bounds__(128)
attn_main(const float* __restrict__ value,
          const float* __restrict__ key,
          const float* __restrict__ q0,
          const float* __restrict__ q1,
          float* __restrict__ out) {
    int warp_global = (blockIdx.x * blockDim.x + threadIdx.x) >> 5;
    if (warp_global >= Nn) return;
    const int n = warp_global;
    const int lane = threadIdx.x & 31;

    // per-lane query slice (4 feats of one channel c = lane)
    const float q_a = q0[n * 32 + lane];
    const float q_b = q1[n * 96 + 3 * lane + 0];
    const float q_c = q1[n * 96 + 3 * lane + 1];
    const float q_d = q1[n * 96 + 3 * lane + 2];

    const int start = g_offset[n];
    const int cnt   = g_count[n];

    float acc0 = 0.f, acc1x = 0.f, acc1y = 0.f, acc1z = 0.f;
    float s = 0.f;  // valid on all lanes of each 4-lane head group

    const int srclane_lo = (lane >> 3) << 2;        // head l/8
    const int srclane_hi = srclane_lo + 16;          // head 4 + l/8
    const float scale = 0.08838834764831845f;        // 1/sqrt(128)
    float* __restrict__ prel = out + (size_t)Nn * 128;

    if (cnt > 0) {
        const int last = cnt - 1;
        int e = g_eidx[start];
        // preload edge 0
        float4 k4 = __ldcs(reinterpret_cast<const float4*>(key + (size_t)e * 128 + 4 * lane));
        const float* vr = value + (size_t)e * 192;
        float v0 = __ldcs(vr + 3 * lane);
        float w1 = __ldcs(vr + 96 + 3 * lane + 0);
        float w2 = __ldcs(vr + 96 + 3 * lane + 1);
        float w3 = __ldcs(vr + 96 + 3 * lane + 2);

        for (int i = 0; i < cnt; i++) {
            // ---- prefetch edge i+1 (clamped; always in-bounds, branchless) ----
            int ip = (i + 1 < cnt) ? (i + 1) : last;
            int en = g_eidx[start + ip];
            float4 k4n = __ldcs(reinterpret_cast<const float4*>(key + (size_t)en * 128 + 4 * lane));
            const float* vn = value + (size_t)en * 192;
            float v0n = __ldcs(vn + 3 * lane);
            float w1n = __ldcs(vn + 96 + 3 * lane + 0);
            float w2n = __ldcs(vn + 96 + 3 * lane + 1);
            float w3n = __ldcs(vn + 96 + 3 * lane + 2);

            // ---- compute edge i ----
            float p = k4.x * q_a + k4.y * q_b + k4.z * q_c + k4.w * q_d;
            p += __shfl_xor_sync(0xffffffffu, p, 1);
            p += __shfl_xor_sync(0xffffffffu, p, 2);
            p *= scale;
            float ex = __expf(p);
            if ((lane & 3) == 0) {
                prel[(size_t)e * 8 + (lane >> 2)] = p;  // prelogits output
                s += ex;
            }
            float ex_lo = __shfl_sync(0xffffffffu, ex, srclane_lo);
            float ex_hi = __shfl_sync(0xffffffffu, ex, srclane_hi);

            acc0  += ex_lo * v0;
            acc1x += ex_hi * w1;
            acc1y += ex_hi * w2;
            acc1z += ex_hi * w3;

            // rotate pipeline
            e = en; k4 = k4n; v0 = v0n; w1 = w1n; w2 = w2n; w3 = w3n;
        }
    }

    float s_lo = __shfl_sync(0xffffffffu, s, srclane_lo);
    float s_hi = __shfl_sync(0xffffffffu, s, srclane_hi);
    float inv_lo = (s_lo > 0.f) ? 1.0f / s_lo : 0.0f;
    float inv_hi = (s_hi > 0.f) ? 1.0f / s_hi : 0.0f;

    out[n * 32 + lane] = acc0 * inv_lo;                 // out_0: (N,32,1)
    float* __restrict__ o1 = out + (size_t)Nn * 32;     // out_1: (N,32,3)
    o1[n * 96 + 3 * lane + 0] = acc1x * inv_hi;
    o1[n * 96 + 3 * lane + 1] = acc1y * inv_hi;
    o1[n * 96 + 3 * lane + 2] = acc1z * inv_hi;
}

extern "C" void kernel_launch(void* const* d_in, const int* in_sizes, int n_in,
                              void* d_out, int out_size) {
    const float* value = (const float*)d_in[0];   // (E,64,3)
    const float* key   = (const float*)d_in[1];   // (E,128)
    const float* q0    = (const float*)d_in[2];   // (N,32,1)
    const float* q1    = (const float*)d_in[3];   // (N,32,3)
    const int*   dst   = (const int*)d_in[4];     // (E,)
    float* out = (float*)d_out;                   // out_0 | out_1 | prelogits

    void* pcount = nullptr;
    cudaGetSymbolAddress(&pcount, g_count);
    cudaMemsetAsync(pcount, 0, Nn * sizeof(int));
    void* ptotal = nullptr;
    cudaGetSymbolAddress(&ptotal, g_total);
    cudaMemsetAsync(ptotal, 0, sizeof(int));

    hist_kernel<<<(Ee + 255) / 256, 256>>>(dst);
    offset_kernel<<<(Nn + 1023) / 1024, 1024>>>();
    scatter_kernel<<<(Ee + 255) / 256, 256>>>(dst);
    attn_main<<<(Nn * 32 + 127) / 128, 128>>>(value, key, q0, q1, out);
}